// round 14
// baseline (speedup 1.0000x reference)
#include <cuda_runtime.h>
#include <cuda_bf16.h>
#include <math.h>
#include <stdint.h>

// Problem constants
#define Bz   4
#define Nn   2048
#define Cc   1024
#define Hh   8
#define Dd   128
#define Mm   (Bz * Nn)          // 8192 tokens
#define C3   (3 * Cc)           // 3072
#define EPS  1e-5f
#define ATT_SCALE 0.08838834764831845f  // 128^-0.5

// ================= PTX helpers =================
__device__ __forceinline__ uint32_t smem_u32(const void* p) {
    uint32_t a;
    asm("{ .reg .u64 t; cvta.to.shared.u64 t, %1; cvt.u32.u64 %0, t; }" : "=r"(a) : "l"(p));
    return a;
}
#define CP_ASYNC(dst, src) \
    asm volatile("cp.async.cg.shared.global [%0], [%1], 16;" :: "r"(dst), "l"(src))
#define CP_COMMIT() asm volatile("cp.async.commit_group;" ::: "memory")
#define CP_WAIT1()  asm volatile("cp.async.wait_group 1;" ::: "memory")
#define CP_WAIT0()  asm volatile("cp.async.wait_group 0;" ::: "memory")

__device__ __forceinline__ void ldsm_x4(uint32_t& r0, uint32_t& r1, uint32_t& r2, uint32_t& r3,
                                        uint32_t addr) {
    asm volatile("ldmatrix.sync.aligned.m8n8.x4.shared.b16 {%0,%1,%2,%3}, [%4];"
                 : "=r"(r0), "=r"(r1), "=r"(r2), "=r"(r3) : "r"(addr));
}
__device__ __forceinline__ void ldsm_x4_t(uint32_t& r0, uint32_t& r1, uint32_t& r2, uint32_t& r3,
                                          uint32_t addr) {
    asm volatile("ldmatrix.sync.aligned.m8n8.x4.trans.shared.b16 {%0,%1,%2,%3}, [%4];"
                 : "=r"(r0), "=r"(r1), "=r"(r2), "=r"(r3) : "r"(addr));
}
__device__ __forceinline__ void mma_bf16(float* d, const uint32_t* a, const uint32_t* b) {
    asm volatile(
        "mma.sync.aligned.m16n8k16.row.col.f32.bf16.bf16.f32 "
        "{%0,%1,%2,%3}, {%4,%5,%6,%7}, {%8,%9}, {%0,%1,%2,%3};"
        : "+f"(d[0]), "+f"(d[1]), "+f"(d[2]), "+f"(d[3])
        : "r"(a[0]), "r"(a[1]), "r"(a[2]), "r"(a[3]), "r"(b[0]), "r"(b[1]));
}

__device__ __forceinline__ void split2(float a, float b, uint32_t& hp, uint32_t& lp) {
    __nv_bfloat16 ha = __float2bfloat16(a), hb = __float2bfloat16(b);
    float ra = a - __bfloat162float(ha), rb = b - __bfloat162float(hb);
    __nv_bfloat16 la = __float2bfloat16(ra), lb = __float2bfloat16(rb);
    hp = (uint32_t)__bfloat16_as_ushort(ha) | ((uint32_t)__bfloat16_as_ushort(hb) << 16);
    lp = (uint32_t)__bfloat16_as_ushort(la) | ((uint32_t)__bfloat16_as_ushort(lb) << 16);
}
__device__ __forceinline__ uint32_t cvt2bf(float a, float b) {
    __nv_bfloat162 t = __floats2bfloat162_rn(a, b);
    return *(uint32_t*)&t;
}

// ================= scratch (device globals) =================
__device__ float g_x1 [Mm * Cc];
__device__ __nv_bfloat16 g_qkv_hi[Mm * C3];
__device__ __nv_bfloat16 g_h_hi   [Mm * Cc], g_h_lo   [Mm * Cc];
__device__ __nv_bfloat16 g_attn_hi[Mm * Cc], g_attn_lo[Mm * Cc];
__device__ __nv_bfloat16 g_h1_hi  [Mm * Cc], g_h1_lo  [Mm * Cc];
__device__ __nv_bfloat16 g_wqkv_hi [C3 * Cc], g_wqkv_lo [C3 * Cc];
__device__ __nv_bfloat16 g_wproj_hi[Cc * Cc], g_wproj_lo[Cc * Cc];
__device__ __nv_bfloat16 g_w1_hi   [Cc * Cc], g_w1_lo   [Cc * Cc];
__device__ __nv_bfloat16 g_w2_hi   [Cc * Cc], g_w2_lo   [Cc * Cc];

// ================= fused fp32 -> bf16 hi/lo converter (all 4 weights) ========
__global__ void cvt_split_all_k(const float* __restrict__ wqkv, const float* __restrict__ wproj,
                                const float* __restrict__ w1, const float* __restrict__ w2,
                                __nv_bfloat16* __restrict__ qkv_hi, __nv_bfloat16* __restrict__ qkv_lo,
                                __nv_bfloat16* __restrict__ proj_hi, __nv_bfloat16* __restrict__ proj_lo,
                                __nv_bfloat16* __restrict__ w1_hi, __nv_bfloat16* __restrict__ w1_lo,
                                __nv_bfloat16* __restrict__ w2_hi, __nv_bfloat16* __restrict__ w2_lo)
{
    int blk = blockIdx.x;
    const float* src;
    __nv_bfloat16 *hi, *lo;
    int local;
    if (blk < 3072)      { src = wqkv;  hi = qkv_hi;  lo = qkv_lo;  local = blk; }
    else if (blk < 4096) { src = wproj; hi = proj_hi; lo = proj_lo; local = blk - 3072; }
    else if (blk < 5120) { src = w1;    hi = w1_hi;   lo = w1_lo;   local = blk - 4096; }
    else                 { src = w2;    hi = w2_hi;   lo = w2_lo;   local = blk - 5120; }
    int i = local * 256 + threadIdx.x;
    float4 v = ((const float4*)src)[i];
    uint32_t h0, l0, h1, l1;
    split2(v.x, v.y, h0, l0);
    split2(v.z, v.w, h1, l1);
    ((uint2*)hi)[i] = make_uint2(h0, h1);
    ((uint2*)lo)[i] = make_uint2(l0, l1);
}

// ================= LayerNorm -> bf16 hi/lo =================
__global__ void layernorm_bf_k(const float* __restrict__ in, const float* __restrict__ g,
                               const float* __restrict__ b,
                               __nv_bfloat16* __restrict__ hi, __nv_bfloat16* __restrict__ lo)
{
    int row = blockIdx.x;
    int t = threadIdx.x;
    const float4* inr = (const float4*)(in + (size_t)row * Cc);
    float4 v = inr[t];
    float s  = v.x + v.y + v.z + v.w;
    float ss = v.x*v.x + v.y*v.y + v.z*v.z + v.w*v.w;
    #pragma unroll
    for (int o = 16; o; o >>= 1) {
        s  += __shfl_xor_sync(0xffffffffu, s,  o);
        ss += __shfl_xor_sync(0xffffffffu, ss, o);
    }
    __shared__ float sm1[8], sm2[8];
    if ((t & 31) == 0) { sm1[t >> 5] = s; sm2[t >> 5] = ss; }
    __syncthreads();
    if (t < 32) {
        s  = (t < 8) ? sm1[t] : 0.f;
        ss = (t < 8) ? sm2[t] : 0.f;
        #pragma unroll
        for (int o = 4; o; o >>= 1) {
            s  += __shfl_xor_sync(0xffffffffu, s,  o);
            ss += __shfl_xor_sync(0xffffffffu, ss, o);
        }
        if (t == 0) { sm1[0] = s; sm2[0] = ss; }
    }
    __syncthreads();
    float mu  = sm1[0] * (1.f / Cc);
    float var = sm2[0] * (1.f / Cc) - mu * mu;
    float inv = rsqrtf(var + EPS);
    float4 gv = ((const float4*)g)[t];
    float4 bv = ((const float4*)b)[t];
    float o0 = (v.x - mu) * inv * gv.x + bv.x;
    float o1 = (v.y - mu) * inv * gv.y + bv.y;
    float o2 = (v.z - mu) * inv * gv.z + bv.z;
    float o3 = (v.w - mu) * inv * gv.w + bv.w;
    uint32_t h0, l0, h1, l1;
    split2(o0, o1, h0, l0);
    split2(o2, o3, h1, l1);
    ((uint2*)(hi + (size_t)row * Cc))[t] = make_uint2(h0, h1);
    ((uint2*)(lo + (size_t)row * Cc))[t] = make_uint2(l0, l1);
}

// ================= mma.sync split-bf16 GEMM (tile 128x256, 1 CTA/SM) ========
// C[M,N] = A[M,K] @ B[N,K]^T via AhiBhi + AhiBlo + AloBhi, fp32 accum.
// 8 warps as 2m x 4n; warp tile 64x64.
// EPI: 1 +bias+res fp32 | 2 +bias,ELU->bf16 split | 3 +bias,ELU,BN,+res fp32
// EPI 4: plain -> bf16 hi only
#define BK       32
#define SSTRIDE  40
#define A_TILE_B (128 * SSTRIDE * 2)   // 10240
#define B_TILE_B (256 * SSTRIDE * 2)   // 20480
#define B_HI_OFF (2 * A_TILE_B)        // 20480
#define B_LO_OFF (B_HI_OFF + B_TILE_B) // 40960
#define STAGE_B  (2 * A_TILE_B + 2 * B_TILE_B)  // 61440
#define HG_SMEM  (2 * STAGE_B)         // 122880

template <int EPI>
__global__ __launch_bounds__(256, 1)
void hgemm_k(const __nv_bfloat16* __restrict__ Ahi, const __nv_bfloat16* __restrict__ Alo,
             const __nv_bfloat16* __restrict__ Bhi, const __nv_bfloat16* __restrict__ Blo,
             float* __restrict__ Cf, __nv_bfloat16* __restrict__ Chi, __nv_bfloat16* __restrict__ Clo,
             const float* __restrict__ bias, const float* __restrict__ res,
             const float* __restrict__ bng, const float* __restrict__ bnb,
             const float* __restrict__ bnm, const float* __restrict__ bnv,
             int Ndim, int Kdim)
{
    extern __shared__ char dsm[];
    const int tid = threadIdx.x;
    const int wid = tid >> 5, lid = tid & 31;
    const int m_blk = blockIdx.y * 128, n_blk = blockIdx.x * 256;
    const int wm = wid >> 2, wn = wid & 3;     // 2m x 4n

    const uint32_t sbase = smem_u32(dsm);

    float acc[4][8][4];
    #pragma unroll
    for (int i = 0; i < 4; i++)
        #pragma unroll
        for (int j = 0; j < 8; j++)
            #pragma unroll
            for (int q = 0; q < 4; q++) acc[i][j][q] = 0.f;

    const int a_row = 64 * wm + (lid & 15);
    const int a_col = (lid >> 4) * 8;
    const int b_row = 64 * wn + ((lid & 16) >> 1) + (lid & 7);
    const int b_col = (lid & 8);

    // stage loader: 3072 cp.asyncs -> 12 per thread
    auto load_stage = [&](int c) {
        const int kk = c * BK;
        const uint32_t sb = sbase + (c & 1) * STAGE_B;
        #pragma unroll
        for (int it = 0; it < 12; ++it) {
            int id = tid + it * 256;
            if (id < 512) {              // A hi
                int row = id >> 2, seg = id & 3;
                uint32_t so = (uint32_t)(row * SSTRIDE + seg * 8) * 2;
                CP_ASYNC(sb + so, Ahi + (size_t)(m_blk + row) * Kdim + kk + seg * 8);
            } else if (id < 1024) {      // A lo
                int loc = id - 512;
                int row = loc >> 2, seg = loc & 3;
                uint32_t so = (uint32_t)(row * SSTRIDE + seg * 8) * 2;
                CP_ASYNC(sb + A_TILE_B + so, Alo + (size_t)(m_blk + row) * Kdim + kk + seg * 8);
            } else if (id < 2048) {      // B hi
                int loc = id - 1024;
                int row = loc >> 2, seg = loc & 3;
                uint32_t so = (uint32_t)(row * SSTRIDE + seg * 8) * 2;
                CP_ASYNC(sb + B_HI_OFF + so, Bhi + (size_t)(n_blk + row) * Kdim + kk + seg * 8);
            } else {                     // B lo
                int loc = id - 2048;
                int row = loc >> 2, seg = loc & 3;
                uint32_t so = (uint32_t)(row * SSTRIDE + seg * 8) * 2;
                CP_ASYNC(sb + B_LO_OFF + so, Blo + (size_t)(n_blk + row) * Kdim + kk + seg * 8);
            }
        }
        CP_COMMIT();
    };

    const int nchunk = Kdim / BK;
    load_stage(0);
    for (int c = 0; c < nchunk; ++c) {
        if (c + 1 < nchunk) { load_stage(c + 1); CP_WAIT1(); }
        else                { CP_WAIT0(); }
        __syncthreads();
        const uint32_t sb = sbase + (c & 1) * STAGE_B;
        #pragma unroll
        for (int k16 = 0; k16 < BK / 16; ++k16) {
            uint32_t ah[4][4], al[4][4];
            #pragma unroll
            for (int i = 0; i < 4; ++i) {
                uint32_t ao = sb + (uint32_t)((a_row + 16 * i) * SSTRIDE + a_col + 16 * k16) * 2;
                ldsm_x4(ah[i][0], ah[i][1], ah[i][2], ah[i][3], ao);
                ldsm_x4(al[i][0], al[i][1], al[i][2], al[i][3], ao + A_TILE_B);
            }
            #pragma unroll
            for (int jj = 0; jj < 4; ++jj) {
                uint32_t bh[2][2], bl[2][2];
                uint32_t bo = sb + B_HI_OFF
                            + (uint32_t)((16 * jj + b_row) * SSTRIDE + b_col + 16 * k16) * 2;
                ldsm_x4(bh[0][0], bh[0][1], bh[1][0], bh[1][1], bo);
                ldsm_x4(bl[0][0], bl[0][1], bl[1][0], bl[1][1], bo + B_TILE_B);
                #pragma unroll
                for (int i = 0; i < 4; ++i) {
                    #pragma unroll
                    for (int t = 0; t < 2; ++t) {
                        mma_bf16(acc[i][2*jj + t], ah[i], bh[t]);
                        mma_bf16(acc[i][2*jj + t], ah[i], bl[t]);
                        mma_bf16(acc[i][2*jj + t], al[i], bh[t]);
                    }
                }
            }
        }
        __syncthreads();
    }

    #pragma unroll
    for (int i = 0; i < 4; ++i) {
        #pragma unroll
        for (int half = 0; half < 2; ++half) {
            const int r = m_blk + 64 * wm + 16 * i + (lid >> 2) + 8 * half;
            #pragma unroll
            for (int j = 0; j < 8; ++j) {
                const int c = n_blk + 64 * wn + 8 * j + 2 * (lid & 3);
                float v0 = acc[i][j][2 * half + 0];
                float v1 = acc[i][j][2 * half + 1];
                if (EPI == 1) {
                    const float2 rv = *(const float2*)(res + (size_t)r * Ndim + c);
                    v0 += __ldg(bias + c)     + rv.x;
                    v1 += __ldg(bias + c + 1) + rv.y;
                } else if (EPI == 2) {
                    v0 += __ldg(bias + c);
                    v1 += __ldg(bias + c + 1);
                    v0 = (v0 > 0.f) ? v0 : expm1f(v0);
                    v1 = (v1 > 0.f) ? v1 : expm1f(v1);
                } else if (EPI == 3) {
                    const float2 rv = *(const float2*)(res + (size_t)r * Ndim + c);
                    v0 += __ldg(bias + c);
                    v1 += __ldg(bias + c + 1);
                    v0 = (v0 > 0.f) ? v0 : expm1f(v0);
                    v1 = (v1 > 0.f) ? v1 : expm1f(v1);
                    v0 = (v0 - __ldg(bnm + c))     * rsqrtf(__ldg(bnv + c) + EPS)     * __ldg(bng + c)     + __ldg(bnb + c)     + rv.x;
                    v1 = (v1 - __ldg(bnm + c + 1)) * rsqrtf(__ldg(bnv + c + 1) + EPS) * __ldg(bng + c + 1) + __ldg(bnb + c + 1) + rv.y;
                }
                if (EPI == 2) {
                    uint32_t hp, lp;
                    split2(v0, v1, hp, lp);
                    *(uint32_t*)(Chi + (size_t)r * Ndim + c) = hp;
                    *(uint32_t*)(Clo + (size_t)r * Ndim + c) = lp;
                } else if (EPI == 4) {
                    *(uint32_t*)(Chi + (size_t)r * Ndim + c) = cvt2bf(v0, v1);
                } else {
                    *(float2*)(Cf + (size_t)r * Ndim + c) = make_float2(v0, v1);
                }
            }
        }
    }
}

// ================= Tensor-core flash attention (pure bf16 QK, 2 CTAs/SM) ====
#define FQSTR     136
#define FQ_B      (128 * FQSTR * 2)        // 34816
#define FK_B      (64 * FQSTR * 2)         // 17408
#define FSTAGE_B  (2 * FK_B)               // 34816
#define FLASH_SMEM (FQ_B + 2 * FSTAGE_B)   // 104448 -> 2 CTAs/SM

__global__ __launch_bounds__(256, 2)
void flash_tc_k(const __nv_bfloat16* __restrict__ qkv_hi,
                __nv_bfloat16* __restrict__ out_hi, __nv_bfloat16* __restrict__ out_lo)
{
    extern __shared__ char fsm[];
    const int tid = threadIdx.x, wid = tid >> 5, lid = tid & 31;
    const int bh_i = blockIdx.y, b = bh_i >> 3, h = bh_i & 7;
    const int q0 = blockIdx.x * 128;
    const size_t base = (size_t)b * Nn * C3 + h * Dd;

    const uint32_t sQ  = smem_u32(fsm);
    const uint32_t sKV = sQ + FQ_B;

    #pragma unroll
    for (int it = 0; it < 8; ++it) {
        int idx = tid + it * 256;
        int row = idx >> 4, seg = idx & 15;
        uint32_t so = (uint32_t)row * (FQSTR * 2) + seg * 16;
        CP_ASYNC(sQ + so, qkv_hi + base + (size_t)(q0 + row) * C3 + seg * 8);
    }

    auto load_kv = [&](int kt) {
        const uint32_t sb = sKV + (kt & 1) * FSTAGE_B;
        #pragma unroll
        for (int it = 0; it < 4; ++it) {
            int idx = tid + it * 256;
            int row = idx >> 4, seg = idx & 15;
            uint32_t so = (uint32_t)row * (FQSTR * 2) + seg * 16;
            size_t gk = base + (size_t)(kt * 64 + row) * C3 + Cc + seg * 8;
            size_t gv = base + (size_t)(kt * 64 + row) * C3 + 2 * Cc + seg * 8;
            CP_ASYNC(sb + so,        qkv_hi + gk);
            CP_ASYNC(sb + FK_B + so, qkv_hi + gv);
        }
        CP_COMMIT();
    };

    load_kv(0);

    const float SCL = ATT_SCALE * 1.4426950408889634f;
    float m0 = -1e30f, m1 = -1e30f, l0 = 0.f, l1 = 0.f;
    float accO[16][4];
    #pragma unroll
    for (int j = 0; j < 16; ++j)
        #pragma unroll
        for (int q = 0; q < 4; ++q) accO[j][q] = 0.f;

    const uint32_t a_off0 = (uint32_t)((16 * wid + (lid & 15)) * FQSTR + (lid >> 4) * 8) * 2;
    const int b_rl = ((lid & 16) >> 1) + (lid & 7);
    const int b_cl = (lid & 8);
    const int v_rl = (lid & 8) + (lid & 7);
    const int v_cl = ((lid & 16) >> 1);

    const int NT = Nn / 64;
    for (int kt = 0; kt < NT; ++kt) {
        if (kt + 1 < NT) { load_kv(kt + 1); CP_WAIT1(); }
        else             { CP_WAIT0(); }
        __syncthreads();
        const uint32_t sb = sKV + (kt & 1) * FSTAGE_B;

        float accS[8][4];
        #pragma unroll
        for (int j = 0; j < 8; ++j)
            #pragma unroll
            for (int q = 0; q < 4; ++q) accS[j][q] = 0.f;

        #pragma unroll
        for (int k16 = 0; k16 < 8; ++k16) {
            uint32_t ah[4];
            uint32_t ao = sQ + a_off0 + (uint32_t)(16 * k16) * 2;
            ldsm_x4(ah[0], ah[1], ah[2], ah[3], ao);
            #pragma unroll
            for (int jj = 0; jj < 4; ++jj) {
                uint32_t bh[2][2];
                uint32_t bo = sb + (uint32_t)((16 * jj + b_rl) * FQSTR + b_cl + 16 * k16) * 2;
                ldsm_x4(bh[0][0], bh[0][1], bh[1][0], bh[1][1], bo);
                mma_bf16(accS[2*jj],     ah, bh[0]);
                mma_bf16(accS[2*jj + 1], ah, bh[1]);
            }
        }

        float mx0 = -1e30f, mx1 = -1e30f;
        #pragma unroll
        for (int j = 0; j < 8; ++j) {
            mx0 = fmaxf(mx0, fmaxf(accS[j][0], accS[j][1]));
            mx1 = fmaxf(mx1, fmaxf(accS[j][2], accS[j][3]));
        }
        mx0 = fmaxf(mx0, __shfl_xor_sync(0xffffffffu, mx0, 1));
        mx0 = fmaxf(mx0, __shfl_xor_sync(0xffffffffu, mx0, 2));
        mx1 = fmaxf(mx1, __shfl_xor_sync(0xffffffffu, mx1, 1));
        mx1 = fmaxf(mx1, __shfl_xor_sync(0xffffffffu, mx1, 2));
        mx0 *= SCL; mx1 *= SCL;
        float mn0 = fmaxf(m0, mx0), mn1 = fmaxf(m1, mx1);
        float al0 = exp2f(m0 - mn0), al1 = exp2f(m1 - mn1);
        m0 = mn0; m1 = mn1;

        float ls0 = 0.f, ls1 = 0.f;
        #pragma unroll
        for (int j = 0; j < 8; ++j) {
            float p0 = exp2f(accS[j][0] * SCL - mn0);
            float p1 = exp2f(accS[j][1] * SCL - mn0);
            float p2 = exp2f(accS[j][2] * SCL - mn1);
            float p3 = exp2f(accS[j][3] * SCL - mn1);
            accS[j][0] = p0; accS[j][1] = p1; accS[j][2] = p2; accS[j][3] = p3;
            ls0 += p0 + p1; ls1 += p2 + p3;
        }
        ls0 += __shfl_xor_sync(0xffffffffu, ls0, 1);
        ls0 += __shfl_xor_sync(0xffffffffu, ls0, 2);
        ls1 += __shfl_xor_sync(0xffffffffu, ls1, 1);
        ls1 += __shfl_xor_sync(0xffffffffu, ls1, 2);
        l0 = l0 * al0 + ls0;
        l1 = l1 * al1 + ls1;

        #pragma unroll
        for (int j = 0; j < 16; ++j) {
            accO[j][0] *= al0; accO[j][1] *= al0;
            accO[j][2] *= al1; accO[j][3] *= al1;
        }

        uint32_t pa[4][4];
        #pragma unroll
        for (int kk = 0; kk < 4; ++kk) {
            pa[kk][0] = cvt2bf(accS[2*kk][0],   accS[2*kk][1]);
            pa[kk][1] = cvt2bf(accS[2*kk][2],   accS[2*kk][3]);
            pa[kk][2] = cvt2bf(accS[2*kk+1][0], accS[2*kk+1][1]);
            pa[kk][3] = cvt2bf(accS[2*kk+1][2], accS[2*kk+1][3]);
        }

        #pragma unroll
        for (int kk = 0; kk < 4; ++kk) {
            #pragma unroll
            for (int jj = 0; jj < 8; ++jj) {
                uint32_t r0, r1, r2, r3;
                uint32_t vo = sb + FK_B
                            + (uint32_t)((16 * kk + v_rl) * FQSTR + 16 * jj + v_cl) * 2;
                ldsm_x4_t(r0, r1, r2, r3, vo);
                uint32_t vb0[2] = {r0, r1}, vb1[2] = {r2, r3};
                mma_bf16(accO[2*jj],     pa[kk], vb0);
                mma_bf16(accO[2*jj + 1], pa[kk], vb1);
            }
        }
        __syncthreads();
    }

    float inv0 = 1.f / l0, inv1 = 1.f / l1;
    const int row0 = q0 + 16 * wid + (lid >> 2);
    #pragma unroll
    for (int j = 0; j < 16; ++j) {
        const int col = h * Dd + 8 * j + 2 * (lid & 3);
        uint32_t hp, lp;
        split2(accO[j][0] * inv0, accO[j][1] * inv0, hp, lp);
        size_t o0 = ((size_t)b * Nn + row0) * Cc + col;
        *(uint32_t*)(out_hi + o0) = hp;
        *(uint32_t*)(out_lo + o0) = lp;
        split2(accO[j][2] * inv1, accO[j][3] * inv1, hp, lp);
        size_t o1 = ((size_t)b * Nn + row0 + 8) * Cc + col;
        *(uint32_t*)(out_hi + o1) = hp;
        *(uint32_t*)(out_lo + o1) = lp;
    }
}

// ================= host launcher =================
extern "C" void kernel_launch(void* const* d_in, const int* in_sizes, int n_in,
                              void* d_out, int out_size)
{
    const float* x       = (const float*)d_in[0];
    const float* ln1_g   = (const float*)d_in[1];
    const float* ln1_b   = (const float*)d_in[2];
    const float* w_qkv   = (const float*)d_in[3];
    const float* w_proj  = (const float*)d_in[4];
    const float* b_proj  = (const float*)d_in[5];
    const float* ln2_g   = (const float*)d_in[6];
    const float* ln2_b   = (const float*)d_in[7];
    const float* w1      = (const float*)d_in[8];
    const float* b1      = (const float*)d_in[9];
    const float* w2      = (const float*)d_in[10];
    const float* b2      = (const float*)d_in[11];
    const float* bn_g    = (const float*)d_in[12];
    const float* bn_b    = (const float*)d_in[13];
    const float* bn_mean = (const float*)d_in[14];
    const float* bn_var  = (const float*)d_in[15];
    float* out = (float*)d_out;

    float *p_x1;
    __nv_bfloat16 *p_qkv_hi;
    __nv_bfloat16 *p_h_hi, *p_h_lo, *p_attn_hi, *p_attn_lo, *p_h1_hi, *p_h1_lo;
    __nv_bfloat16 *p_wqkv_hi, *p_wqkv_lo, *p_wproj_hi, *p_wproj_lo;
    __nv_bfloat16 *p_w1_hi, *p_w1_lo, *p_w2_hi, *p_w2_lo;
    cudaGetSymbolAddress((void**)&p_x1,       g_x1);
    cudaGetSymbolAddress((void**)&p_qkv_hi,   g_qkv_hi);
    cudaGetSymbolAddress((void**)&p_h_hi,     g_h_hi);
    cudaGetSymbolAddress((void**)&p_h_lo,     g_h_lo);
    cudaGetSymbolAddress((void**)&p_attn_hi,  g_attn_hi);
    cudaGetSymbolAddress((void**)&p_attn_lo,  g_attn_lo);
    cudaGetSymbolAddress((void**)&p_h1_hi,    g_h1_hi);
    cudaGetSymbolAddress((void**)&p_h1_lo,    g_h1_lo);
    cudaGetSymbolAddress((void**)&p_wqkv_hi,  g_wqkv_hi);
    cudaGetSymbolAddress((void**)&p_wqkv_lo,  g_wqkv_lo);
    cudaGetSymbolAddress((void**)&p_wproj_hi, g_wproj_hi);
    cudaGetSymbolAddress((void**)&p_wproj_lo, g_wproj_lo);
    cudaGetSymbolAddress((void**)&p_w1_hi,    g_w1_hi);
    cudaGetSymbolAddress((void**)&p_w1_lo,    g_w1_lo);
    cudaGetSymbolAddress((void**)&p_w2_hi,    g_w2_hi);
    cudaGetSymbolAddress((void**)&p_w2_lo,    g_w2_lo);

    cudaFuncSetAttribute(hgemm_k<1>, cudaFuncAttributeMaxDynamicSharedMemorySize, HG_SMEM);
    cudaFuncSetAttribute(hgemm_k<2>, cudaFuncAttributeMaxDynamicSharedMemorySize, HG_SMEM);
    cudaFuncSetAttribute(hgemm_k<3>, cudaFuncAttributeMaxDynamicSharedMemorySize, HG_SMEM);
    cudaFuncSetAttribute(hgemm_k<4>, cudaFuncAttributeMaxDynamicSharedMemorySize, HG_SMEM);
    cudaFuncSetAttribute(flash_tc_k, cudaFuncAttributeMaxDynamicSharedMemorySize, FLASH_SMEM);

    // fused weight splits (one launch)
    cvt_split_all_k<<<6144, 256>>>(w_qkv, w_proj, w1, w2,
                                   p_wqkv_hi, p_wqkv_lo, p_wproj_hi, p_wproj_lo,
                                   p_w1_hi, p_w1_lo, p_w2_hi, p_w2_lo);

    // LN1 -> hi/lo
    layernorm_bf_k<<<Mm, 256>>>(x, ln1_g, ln1_b, p_h_hi, p_h_lo);

    // QKV GEMM -> bf16 hi only (EPI 4)
    hgemm_k<4><<<dim3(C3 / 256, Mm / 128), 256, HG_SMEM>>>(
        p_h_hi, p_h_lo, p_wqkv_hi, p_wqkv_lo,
        nullptr, p_qkv_hi, nullptr,
        nullptr, nullptr, nullptr, nullptr, nullptr, nullptr,
        C3, Cc);

    // Tensor-core flash attention -> attn hi/lo
    flash_tc_k<<<dim3(Nn / 128, Bz * Hh), 256, FLASH_SMEM>>>(
        p_qkv_hi, p_attn_hi, p_attn_lo);

    // proj GEMM + bias + residual -> x1 fp32 (EPI 1)
    hgemm_k<1><<<dim3(Cc / 256, Mm / 128), 256, HG_SMEM>>>(
        p_attn_hi, p_attn_lo, p_wproj_hi, p_wproj_lo,
        p_x1, nullptr, nullptr,
        b_proj, x, nullptr, nullptr, nullptr, nullptr,
        Cc, Cc);

    // LN2 -> hi/lo
    layernorm_bf_k<<<Mm, 256>>>(p_x1, ln2_g, ln2_b, p_h_hi, p_h_lo);

    // MLP1: ELU(h @ w1^T + b1) -> h1 hi/lo (EPI 2)
    hgemm_k<2><<<dim3(Cc / 256, Mm / 128), 256, HG_SMEM>>>(
        p_h_hi, p_h_lo, p_w1_hi, p_w1_lo,
        nullptr, p_h1_hi, p_h1_lo,
        b1, nullptr, nullptr, nullptr, nullptr, nullptr,
        Cc, Cc);

    // MLP2: out = x1 + BN(ELU(h1 @ w2^T + b2)) (EPI 3)
    hgemm_k<3><<<dim3(Cc / 256, Mm / 128), 256, HG_SMEM>>>(
        p_h1_hi, p_h1_lo, p_w2_hi, p_w2_lo,
        out, nullptr, nullptr,
        b2, p_x1, bn_g, bn_b, bn_mean, bn_var,
        Cc, Cc);
}

// round 15
// speedup vs baseline: 1.1158x; 1.1158x over previous
#include <cuda_runtime.h>
#include <cuda_bf16.h>
#include <math.h>
#include <stdint.h>

// Problem constants
#define Bz   4
#define Nn   2048
#define Cc   1024
#define Hh   8
#define Dd   128
#define Mm   (Bz * Nn)          // 8192 tokens
#define C3   (3 * Cc)           // 3072
#define EPS  1e-5f
#define ATT_SCALE 0.08838834764831845f  // 128^-0.5

// ================= PTX helpers =================
__device__ __forceinline__ uint32_t smem_u32(const void* p) {
    uint32_t a;
    asm("{ .reg .u64 t; cvta.to.shared.u64 t, %1; cvt.u32.u64 %0, t; }" : "=r"(a) : "l"(p));
    return a;
}
#define CP_ASYNC(dst, src) \
    asm volatile("cp.async.cg.shared.global [%0], [%1], 16;" :: "r"(dst), "l"(src))
#define CP_COMMIT() asm volatile("cp.async.commit_group;" ::: "memory")
#define CP_WAIT1()  asm volatile("cp.async.wait_group 1;" ::: "memory")
#define CP_WAIT0()  asm volatile("cp.async.wait_group 0;" ::: "memory")

__device__ __forceinline__ void ldsm_x4(uint32_t& r0, uint32_t& r1, uint32_t& r2, uint32_t& r3,
                                        uint32_t addr) {
    asm volatile("ldmatrix.sync.aligned.m8n8.x4.shared.b16 {%0,%1,%2,%3}, [%4];"
                 : "=r"(r0), "=r"(r1), "=r"(r2), "=r"(r3) : "r"(addr));
}
__device__ __forceinline__ void ldsm_x4_t(uint32_t& r0, uint32_t& r1, uint32_t& r2, uint32_t& r3,
                                          uint32_t addr) {
    asm volatile("ldmatrix.sync.aligned.m8n8.x4.trans.shared.b16 {%0,%1,%2,%3}, [%4];"
                 : "=r"(r0), "=r"(r1), "=r"(r2), "=r"(r3) : "r"(addr));
}
__device__ __forceinline__ void mma_bf16(float* d, const uint32_t* a, const uint32_t* b) {
    asm volatile(
        "mma.sync.aligned.m16n8k16.row.col.f32.bf16.bf16.f32 "
        "{%0,%1,%2,%3}, {%4,%5,%6,%7}, {%8,%9}, {%0,%1,%2,%3};"
        : "+f"(d[0]), "+f"(d[1]), "+f"(d[2]), "+f"(d[3])
        : "r"(a[0]), "r"(a[1]), "r"(a[2]), "r"(a[3]), "r"(b[0]), "r"(b[1]));
}

__device__ __forceinline__ void split2(float a, float b, uint32_t& hp, uint32_t& lp) {
    __nv_bfloat16 ha = __float2bfloat16(a), hb = __float2bfloat16(b);
    float ra = a - __bfloat162float(ha), rb = b - __bfloat162float(hb);
    __nv_bfloat16 la = __float2bfloat16(ra), lb = __float2bfloat16(rb);
    hp = (uint32_t)__bfloat16_as_ushort(ha) | ((uint32_t)__bfloat16_as_ushort(hb) << 16);
    lp = (uint32_t)__bfloat16_as_ushort(la) | ((uint32_t)__bfloat16_as_ushort(lb) << 16);
}
__device__ __forceinline__ uint32_t cvt2bf(float a, float b) {
    __nv_bfloat162 t = __floats2bfloat162_rn(a, b);
    return *(uint32_t*)&t;
}

// ================= scratch (device globals) =================
__device__ float g_x1 [Mm * Cc];
__device__ __nv_bfloat16 g_qkv_hi[Mm * C3];
__device__ __nv_bfloat16 g_h_hi   [Mm * Cc], g_h_lo   [Mm * Cc];
__device__ __nv_bfloat16 g_attn_hi[Mm * Cc], g_attn_lo[Mm * Cc];
__device__ __nv_bfloat16 g_h1_hi  [Mm * Cc], g_h1_lo  [Mm * Cc];
__device__ __nv_bfloat16 g_wqkv_hi [C3 * Cc], g_wqkv_lo [C3 * Cc];
__device__ __nv_bfloat16 g_wproj_hi[Cc * Cc], g_wproj_lo[Cc * Cc];
__device__ __nv_bfloat16 g_w1_hi   [Cc * Cc], g_w1_lo   [Cc * Cc];
__device__ __nv_bfloat16 g_w2_hi   [Cc * Cc], g_w2_lo   [Cc * Cc];

// ================= fused fp32 -> bf16 hi/lo converter (all 4 weights) ========
__global__ void cvt_split_all_k(const float* __restrict__ wqkv, const float* __restrict__ wproj,
                                const float* __restrict__ w1, const float* __restrict__ w2,
                                __nv_bfloat16* __restrict__ qkv_hi, __nv_bfloat16* __restrict__ qkv_lo,
                                __nv_bfloat16* __restrict__ proj_hi, __nv_bfloat16* __restrict__ proj_lo,
                                __nv_bfloat16* __restrict__ w1_hi, __nv_bfloat16* __restrict__ w1_lo,
                                __nv_bfloat16* __restrict__ w2_hi, __nv_bfloat16* __restrict__ w2_lo)
{
    int blk = blockIdx.x;
    const float* src;
    __nv_bfloat16 *hi, *lo;
    int local;
    if (blk < 3072)      { src = wqkv;  hi = qkv_hi;  lo = qkv_lo;  local = blk; }
    else if (blk < 4096) { src = wproj; hi = proj_hi; lo = proj_lo; local = blk - 3072; }
    else if (blk < 5120) { src = w1;    hi = w1_hi;   lo = w1_lo;   local = blk - 4096; }
    else                 { src = w2;    hi = w2_hi;   lo = w2_lo;   local = blk - 5120; }
    int i = local * 256 + threadIdx.x;
    float4 v = ((const float4*)src)[i];
    uint32_t h0, l0, h1, l1;
    split2(v.x, v.y, h0, l0);
    split2(v.z, v.w, h1, l1);
    ((uint2*)hi)[i] = make_uint2(h0, h1);
    ((uint2*)lo)[i] = make_uint2(l0, l1);
}

// ================= LayerNorm -> bf16 hi/lo =================
__global__ void layernorm_bf_k(const float* __restrict__ in, const float* __restrict__ g,
                               const float* __restrict__ b,
                               __nv_bfloat16* __restrict__ hi, __nv_bfloat16* __restrict__ lo)
{
    int row = blockIdx.x;
    int t = threadIdx.x;
    const float4* inr = (const float4*)(in + (size_t)row * Cc);
    float4 v = inr[t];
    float s  = v.x + v.y + v.z + v.w;
    float ss = v.x*v.x + v.y*v.y + v.z*v.z + v.w*v.w;
    #pragma unroll
    for (int o = 16; o; o >>= 1) {
        s  += __shfl_xor_sync(0xffffffffu, s,  o);
        ss += __shfl_xor_sync(0xffffffffu, ss, o);
    }
    __shared__ float sm1[8], sm2[8];
    if ((t & 31) == 0) { sm1[t >> 5] = s; sm2[t >> 5] = ss; }
    __syncthreads();
    if (t < 32) {
        s  = (t < 8) ? sm1[t] : 0.f;
        ss = (t < 8) ? sm2[t] : 0.f;
        #pragma unroll
        for (int o = 4; o; o >>= 1) {
            s  += __shfl_xor_sync(0xffffffffu, s,  o);
            ss += __shfl_xor_sync(0xffffffffu, ss, o);
        }
        if (t == 0) { sm1[0] = s; sm2[0] = ss; }
    }
    __syncthreads();
    float mu  = sm1[0] * (1.f / Cc);
    float var = sm2[0] * (1.f / Cc) - mu * mu;
    float inv = rsqrtf(var + EPS);
    float4 gv = ((const float4*)g)[t];
    float4 bv = ((const float4*)b)[t];
    float o0 = (v.x - mu) * inv * gv.x + bv.x;
    float o1 = (v.y - mu) * inv * gv.y + bv.y;
    float o2 = (v.z - mu) * inv * gv.z + bv.z;
    float o3 = (v.w - mu) * inv * gv.w + bv.w;
    uint32_t h0, l0, h1, l1;
    split2(o0, o1, h0, l0);
    split2(o2, o3, h1, l1);
    ((uint2*)(hi + (size_t)row * Cc))[t] = make_uint2(h0, h1);
    ((uint2*)(lo + (size_t)row * Cc))[t] = make_uint2(l0, l1);
}

// ================= mma.sync split-bf16 GEMM =================
// Tile 128x128, BK=32, 4 warps (2m x 2n, warp tile 64x64), 2 CTAs/SM.
// C[M,N] = A[M,K] @ B[N,K]^T via AhiBhi + AhiBlo + AloBhi, fp32 accum.
// EPI: 1 +bias+res fp32 | 2 +bias,ELU->bf16 split | 3 +bias,ELU,BN,+res fp32
// EPI 4: plain -> bf16 hi only
#define BK      32
#define SSTRIDE 40
#define TILE_B  (128 * SSTRIDE * 2)    // 10240
#define STAGE_B (4 * TILE_B)           // 40960
#define HG_SMEM (2 * STAGE_B)          // 81920 -> 2 CTAs/SM

template <int EPI>
__global__ __launch_bounds__(128, 2)
void hgemm_k(const __nv_bfloat16* __restrict__ Ahi, const __nv_bfloat16* __restrict__ Alo,
             const __nv_bfloat16* __restrict__ Bhi, const __nv_bfloat16* __restrict__ Blo,
             float* __restrict__ Cf, __nv_bfloat16* __restrict__ Chi, __nv_bfloat16* __restrict__ Clo,
             const float* __restrict__ bias, const float* __restrict__ res,
             const float* __restrict__ bng, const float* __restrict__ bnb,
             const float* __restrict__ bnm, const float* __restrict__ bnv,
             int Ndim, int Kdim)
{
    extern __shared__ char dsm[];
    const int tid = threadIdx.x;
    const int wid = tid >> 5, lid = tid & 31;
    const int m_blk = blockIdx.y * 128, n_blk = blockIdx.x * 128;
    const int wm = wid >> 1, wn = wid & 1;     // 2m x 2n, warp tile 64x64

    const uint32_t sbase = smem_u32(dsm);

    float acc[4][8][4];
    #pragma unroll
    for (int i = 0; i < 4; i++)
        #pragma unroll
        for (int j = 0; j < 8; j++)
            #pragma unroll
            for (int q = 0; q < 4; q++) acc[i][j][q] = 0.f;

    const int a_row = 64 * wm + (lid & 15);
    const int a_col = (lid >> 4) * 8;
    const int b_row = 64 * wn + ((lid & 16) >> 1) + (lid & 7);
    const int b_col = (lid & 8);

    // stage loader: 2048 cp.asyncs over 128 threads -> 16 per thread
    auto load_stage = [&](int c) {
        const int kk = c * BK;
        const uint32_t sb = sbase + (c & 1) * STAGE_B;
        #pragma unroll
        for (int it = 0; it < 16; ++it) {
            int id = tid + it * 128;
            int loc = id & 511;
            int row = loc >> 2, seg = loc & 3;
            uint32_t so = (uint32_t)(row * SSTRIDE + seg * 8) * 2;
            if (id < 512) {
                CP_ASYNC(sb + so, Ahi + (size_t)(m_blk + row) * Kdim + kk + seg * 8);
            } else if (id < 1024) {
                CP_ASYNC(sb + TILE_B + so, Alo + (size_t)(m_blk + row) * Kdim + kk + seg * 8);
            } else if (id < 1536) {
                CP_ASYNC(sb + 2 * TILE_B + so, Bhi + (size_t)(n_blk + row) * Kdim + kk + seg * 8);
            } else {
                CP_ASYNC(sb + 3 * TILE_B + so, Blo + (size_t)(n_blk + row) * Kdim + kk + seg * 8);
            }
        }
        CP_COMMIT();
    };

    const int nchunk = Kdim / BK;
    load_stage(0);
    for (int c = 0; c < nchunk; ++c) {
        if (c + 1 < nchunk) { load_stage(c + 1); CP_WAIT1(); }
        else                { CP_WAIT0(); }
        __syncthreads();
        const uint32_t sb = sbase + (c & 1) * STAGE_B;
        #pragma unroll
        for (int k16 = 0; k16 < BK / 16; ++k16) {
            uint32_t ah[4][4], al[4][4];
            #pragma unroll
            for (int i = 0; i < 4; ++i) {
                uint32_t ao = sb + (uint32_t)((a_row + 16 * i) * SSTRIDE + a_col + 16 * k16) * 2;
                ldsm_x4(ah[i][0], ah[i][1], ah[i][2], ah[i][3], ao);
                ldsm_x4(al[i][0], al[i][1], al[i][2], al[i][3], ao + TILE_B);
            }
            #pragma unroll
            for (int jj = 0; jj < 4; ++jj) {
                uint32_t bh[2][2], bl[2][2];
                uint32_t bo = sb + 2 * TILE_B
                            + (uint32_t)((16 * jj + b_row) * SSTRIDE + b_col + 16 * k16) * 2;
                ldsm_x4(bh[0][0], bh[0][1], bh[1][0], bh[1][1], bo);
                ldsm_x4(bl[0][0], bl[0][1], bl[1][0], bl[1][1], bo + TILE_B);
                #pragma unroll
                for (int i = 0; i < 4; ++i) {
                    #pragma unroll
                    for (int t = 0; t < 2; ++t) {
                        mma_bf16(acc[i][2*jj + t], ah[i], bh[t]);
                        mma_bf16(acc[i][2*jj + t], ah[i], bl[t]);
                        mma_bf16(acc[i][2*jj + t], al[i], bh[t]);
                    }
                }
            }
        }
        __syncthreads();
    }

    #pragma unroll
    for (int i = 0; i < 4; ++i) {
        #pragma unroll
        for (int half = 0; half < 2; ++half) {
            const int r = m_blk + 64 * wm + 16 * i + (lid >> 2) + 8 * half;
            #pragma unroll
            for (int j = 0; j < 8; ++j) {
                const int c = n_blk + 64 * wn + 8 * j + 2 * (lid & 3);
                float v0 = acc[i][j][2 * half + 0];
                float v1 = acc[i][j][2 * half + 1];
                if (EPI == 1) {
                    const float2 rv = *(const float2*)(res + (size_t)r * Ndim + c);
                    v0 += __ldg(bias + c)     + rv.x;
                    v1 += __ldg(bias + c + 1) + rv.y;
                } else if (EPI == 2) {
                    v0 += __ldg(bias + c);
                    v1 += __ldg(bias + c + 1);
                    v0 = (v0 > 0.f) ? v0 : expm1f(v0);
                    v1 = (v1 > 0.f) ? v1 : expm1f(v1);
                } else if (EPI == 3) {
                    const float2 rv = *(const float2*)(res + (size_t)r * Ndim + c);
                    v0 += __ldg(bias + c);
                    v1 += __ldg(bias + c + 1);
                    v0 = (v0 > 0.f) ? v0 : expm1f(v0);
                    v1 = (v1 > 0.f) ? v1 : expm1f(v1);
                    v0 = (v0 - __ldg(bnm + c))     * rsqrtf(__ldg(bnv + c) + EPS)     * __ldg(bng + c)     + __ldg(bnb + c)     + rv.x;
                    v1 = (v1 - __ldg(bnm + c + 1)) * rsqrtf(__ldg(bnv + c + 1) + EPS) * __ldg(bng + c + 1) + __ldg(bnb + c + 1) + rv.y;
                }
                if (EPI == 2) {
                    uint32_t hp, lp;
                    split2(v0, v1, hp, lp);
                    *(uint32_t*)(Chi + (size_t)r * Ndim + c) = hp;
                    *(uint32_t*)(Clo + (size_t)r * Ndim + c) = lp;
                } else if (EPI == 4) {
                    *(uint32_t*)(Chi + (size_t)r * Ndim + c) = cvt2bf(v0, v1);
                } else {
                    *(float2*)(Cf + (size_t)r * Ndim + c) = make_float2(v0, v1);
                }
            }
        }
    }
}

// ================= Tensor-core flash attention =================
// BQ=128, BK=64, 4 warps x 32 q-rows, 128 threads, 2 CTAs/SM.
#define FQSTR     136
#define FQ_B      (128 * FQSTR * 2)        // 34816
#define FK_B      (64 * FQSTR * 2)         // 17408
#define FSTAGE_B  (2 * FK_B)               // 34816
#define FLASH_SMEM (FQ_B + 2 * FSTAGE_B)   // 104448 -> 2 CTAs/SM

__global__ __launch_bounds__(128, 2)
void flash_tc_k(const __nv_bfloat16* __restrict__ qkv_hi,
                __nv_bfloat16* __restrict__ out_hi, __nv_bfloat16* __restrict__ out_lo)
{
    extern __shared__ char fsm[];
    const int tid = threadIdx.x, wid = tid >> 5, lid = tid & 31;
    const int bh_i = blockIdx.y, b = bh_i >> 3, h = bh_i & 7;
    const int q0 = blockIdx.x * 128;
    const size_t base = (size_t)b * Nn * C3 + h * Dd;

    const uint32_t sQ  = smem_u32(fsm);
    const uint32_t sKV = sQ + FQ_B;

    // Q load: 2048 transfers over 128 threads
    #pragma unroll
    for (int it = 0; it < 16; ++it) {
        int idx = tid + it * 128;
        int row = idx >> 4, seg = idx & 15;
        uint32_t so = (uint32_t)row * (FQSTR * 2) + seg * 16;
        CP_ASYNC(sQ + so, qkv_hi + base + (size_t)(q0 + row) * C3 + seg * 8);
    }

    auto load_kv = [&](int kt) {
        const uint32_t sb = sKV + (kt & 1) * FSTAGE_B;
        #pragma unroll
        for (int it = 0; it < 8; ++it) {
            int idx = tid + it * 128;
            int row = idx >> 4, seg = idx & 15;
            uint32_t so = (uint32_t)row * (FQSTR * 2) + seg * 16;
            size_t gk = base + (size_t)(kt * 64 + row) * C3 + Cc + seg * 8;
            size_t gv = base + (size_t)(kt * 64 + row) * C3 + 2 * Cc + seg * 8;
            CP_ASYNC(sb + so,        qkv_hi + gk);
            CP_ASYNC(sb + FK_B + so, qkv_hi + gv);
        }
        CP_COMMIT();
    };

    load_kv(0);

    const float SCL = ATT_SCALE * 1.4426950408889634f;
    float mst[2][2], lst[2][2];
    #pragma unroll
    for (int m = 0; m < 2; ++m) {
        mst[m][0] = -1e30f; mst[m][1] = -1e30f;
        lst[m][0] = 0.f;    lst[m][1] = 0.f;
    }
    float accO[2][16][4];
    #pragma unroll
    for (int m = 0; m < 2; ++m)
        #pragma unroll
        for (int j = 0; j < 16; ++j)
            #pragma unroll
            for (int q = 0; q < 4; ++q) accO[m][j][q] = 0.f;

    const int b_rl = ((lid & 16) >> 1) + (lid & 7);
    const int b_cl = (lid & 8);
    const int v_rl = (lid & 8) + (lid & 7);
    const int v_cl = ((lid & 16) >> 1);

    const int NT = Nn / 64;
    for (int kt = 0; kt < NT; ++kt) {
        if (kt + 1 < NT) { load_kv(kt + 1); CP_WAIT1(); }
        else             { CP_WAIT0(); }
        __syncthreads();
        const uint32_t sb = sKV + (kt & 1) * FSTAGE_B;

        // ---- S = Q K^T (bf16): warp covers 32 q-rows x 64 k-cols ----
        float accS[2][8][4];
        #pragma unroll
        for (int m = 0; m < 2; ++m)
            #pragma unroll
            for (int j = 0; j < 8; ++j)
                #pragma unroll
                for (int q = 0; q < 4; ++q) accS[m][j][q] = 0.f;

        #pragma unroll
        for (int k16 = 0; k16 < 8; ++k16) {
            uint32_t ah[2][4];
            #pragma unroll
            for (int m = 0; m < 2; ++m) {
                uint32_t ao = sQ + (uint32_t)((32 * wid + 16 * m + (lid & 15)) * FQSTR
                                              + (lid >> 4) * 8 + 16 * k16) * 2;
                ldsm_x4(ah[m][0], ah[m][1], ah[m][2], ah[m][3], ao);
            }
            #pragma unroll
            for (int jj = 0; jj < 4; ++jj) {
                uint32_t bh[2][2];
                uint32_t bo = sb + (uint32_t)((16 * jj + b_rl) * FQSTR + b_cl + 16 * k16) * 2;
                ldsm_x4(bh[0][0], bh[0][1], bh[1][0], bh[1][1], bo);
                #pragma unroll
                for (int m = 0; m < 2; ++m) {
                    mma_bf16(accS[m][2*jj],     ah[m], bh[0]);
                    mma_bf16(accS[m][2*jj + 1], ah[m], bh[1]);
                }
            }
        }

        // ---- online softmax + P fragments ----
        uint32_t pa[2][4][4];
        #pragma unroll
        for (int m = 0; m < 2; ++m) {
            float mx0 = -1e30f, mx1 = -1e30f;
            #pragma unroll
            for (int j = 0; j < 8; ++j) {
                mx0 = fmaxf(mx0, fmaxf(accS[m][j][0], accS[m][j][1]));
                mx1 = fmaxf(mx1, fmaxf(accS[m][j][2], accS[m][j][3]));
            }
            mx0 = fmaxf(mx0, __shfl_xor_sync(0xffffffffu, mx0, 1));
            mx0 = fmaxf(mx0, __shfl_xor_sync(0xffffffffu, mx0, 2));
            mx1 = fmaxf(mx1, __shfl_xor_sync(0xffffffffu, mx1, 1));
            mx1 = fmaxf(mx1, __shfl_xor_sync(0xffffffffu, mx1, 2));
            mx0 *= SCL; mx1 *= SCL;
            float mn0 = fmaxf(mst[m][0], mx0), mn1 = fmaxf(mst[m][1], mx1);
            float al0 = exp2f(mst[m][0] - mn0), al1 = exp2f(mst[m][1] - mn1);
            mst[m][0] = mn0; mst[m][1] = mn1;

            float ls0 = 0.f, ls1 = 0.f;
            #pragma unroll
            for (int j = 0; j < 8; ++j) {
                float p0 = exp2f(accS[m][j][0] * SCL - mn0);
                float p1 = exp2f(accS[m][j][1] * SCL - mn0);
                float p2 = exp2f(accS[m][j][2] * SCL - mn1);
                float p3 = exp2f(accS[m][j][3] * SCL - mn1);
                accS[m][j][0] = p0; accS[m][j][1] = p1;
                accS[m][j][2] = p2; accS[m][j][3] = p3;
                ls0 += p0 + p1; ls1 += p2 + p3;
            }
            ls0 += __shfl_xor_sync(0xffffffffu, ls0, 1);
            ls0 += __shfl_xor_sync(0xffffffffu, ls0, 2);
            ls1 += __shfl_xor_sync(0xffffffffu, ls1, 1);
            ls1 += __shfl_xor_sync(0xffffffffu, ls1, 2);
            lst[m][0] = lst[m][0] * al0 + ls0;
            lst[m][1] = lst[m][1] * al1 + ls1;

            #pragma unroll
            for (int j = 0; j < 16; ++j) {
                accO[m][j][0] *= al0; accO[m][j][1] *= al0;
                accO[m][j][2] *= al1; accO[m][j][3] *= al1;
            }

            #pragma unroll
            for (int kk = 0; kk < 4; ++kk) {
                pa[m][kk][0] = cvt2bf(accS[m][2*kk][0],   accS[m][2*kk][1]);
                pa[m][kk][1] = cvt2bf(accS[m][2*kk][2],   accS[m][2*kk][3]);
                pa[m][kk][2] = cvt2bf(accS[m][2*kk+1][0], accS[m][2*kk+1][1]);
                pa[m][kk][3] = cvt2bf(accS[m][2*kk+1][2], accS[m][2*kk+1][3]);
            }
        }

        // ---- O += P V  (V fragments shared across both m) ----
        #pragma unroll
        for (int kk = 0; kk < 4; ++kk) {
            #pragma unroll
            for (int jj = 0; jj < 8; ++jj) {
                uint32_t r0, r1, r2, r3;
                uint32_t vo = sb + FK_B
                            + (uint32_t)((16 * kk + v_rl) * FQSTR + 16 * jj + v_cl) * 2;
                ldsm_x4_t(r0, r1, r2, r3, vo);
                uint32_t vb0[2] = {r0, r1}, vb1[2] = {r2, r3};
                #pragma unroll
                for (int m = 0; m < 2; ++m) {
                    mma_bf16(accO[m][2*jj],     pa[m][kk], vb0);
                    mma_bf16(accO[m][2*jj + 1], pa[m][kk], vb1);
                }
            }
        }
        __syncthreads();
    }

    // ---- epilogue ----
    #pragma unroll
    for (int m = 0; m < 2; ++m) {
        float inv0 = 1.f / lst[m][0], inv1 = 1.f / lst[m][1];
        const int row0 = q0 + 32 * wid + 16 * m + (lid >> 2);
        #pragma unroll
        for (int j = 0; j < 16; ++j) {
            const int col = h * Dd + 8 * j + 2 * (lid & 3);
            uint32_t hp, lp;
            split2(accO[m][j][0] * inv0, accO[m][j][1] * inv0, hp, lp);
            size_t o0 = ((size_t)b * Nn + row0) * Cc + col;
            *(uint32_t*)(out_hi + o0) = hp;
            *(uint32_t*)(out_lo + o0) = lp;
            split2(accO[m][j][2] * inv1, accO[m][j][3] * inv1, hp, lp);
            size_t o1 = ((size_t)b * Nn + row0 + 8) * Cc + col;
            *(uint32_t*)(out_hi + o1) = hp;
            *(uint32_t*)(out_lo + o1) = lp;
        }
    }
}

// ================= host launcher =================
extern "C" void kernel_launch(void* const* d_in, const int* in_sizes, int n_in,
                              void* d_out, int out_size)
{
    const float* x       = (const float*)d_in[0];
    const float* ln1_g   = (const float*)d_in[1];
    const float* ln1_b   = (const float*)d_in[2];
    const float* w_qkv   = (const float*)d_in[3];
    const float* w_proj  = (const float*)d_in[4];
    const float* b_proj  = (const float*)d_in[5];
    const float* ln2_g   = (const float*)d_in[6];
    const float* ln2_b   = (const float*)d_in[7];
    const float* w1      = (const float*)d_in[8];
    const float* b1      = (const float*)d_in[9];
    const float* w2      = (const float*)d_in[10];
    const float* b2      = (const float*)d_in[11];
    const float* bn_g    = (const float*)d_in[12];
    const float* bn_b    = (const float*)d_in[13];
    const float* bn_mean = (const float*)d_in[14];
    const float* bn_var  = (const float*)d_in[15];
    float* out = (float*)d_out;

    float *p_x1;
    __nv_bfloat16 *p_qkv_hi;
    __nv_bfloat16 *p_h_hi, *p_h_lo, *p_attn_hi, *p_attn_lo, *p_h1_hi, *p_h1_lo;
    __nv_bfloat16 *p_wqkv_hi, *p_wqkv_lo, *p_wproj_hi, *p_wproj_lo;
    __nv_bfloat16 *p_w1_hi, *p_w1_lo, *p_w2_hi, *p_w2_lo;
    cudaGetSymbolAddress((void**)&p_x1,       g_x1);
    cudaGetSymbolAddress((void**)&p_qkv_hi,   g_qkv_hi);
    cudaGetSymbolAddress((void**)&p_h_hi,     g_h_hi);
    cudaGetSymbolAddress((void**)&p_h_lo,     g_h_lo);
    cudaGetSymbolAddress((void**)&p_attn_hi,  g_attn_hi);
    cudaGetSymbolAddress((void**)&p_attn_lo,  g_attn_lo);
    cudaGetSymbolAddress((void**)&p_h1_hi,    g_h1_hi);
    cudaGetSymbolAddress((void**)&p_h1_lo,    g_h1_lo);
    cudaGetSymbolAddress((void**)&p_wqkv_hi,  g_wqkv_hi);
    cudaGetSymbolAddress((void**)&p_wqkv_lo,  g_wqkv_lo);
    cudaGetSymbolAddress((void**)&p_wproj_hi, g_wproj_hi);
    cudaGetSymbolAddress((void**)&p_wproj_lo, g_wproj_lo);
    cudaGetSymbolAddress((void**)&p_w1_hi,    g_w1_hi);
    cudaGetSymbolAddress((void**)&p_w1_lo,    g_w1_lo);
    cudaGetSymbolAddress((void**)&p_w2_hi,    g_w2_hi);
    cudaGetSymbolAddress((void**)&p_w2_lo,    g_w2_lo);

    cudaFuncSetAttribute(hgemm_k<1>, cudaFuncAttributeMaxDynamicSharedMemorySize, HG_SMEM);
    cudaFuncSetAttribute(hgemm_k<2>, cudaFuncAttributeMaxDynamicSharedMemorySize, HG_SMEM);
    cudaFuncSetAttribute(hgemm_k<3>, cudaFuncAttributeMaxDynamicSharedMemorySize, HG_SMEM);
    cudaFuncSetAttribute(hgemm_k<4>, cudaFuncAttributeMaxDynamicSharedMemorySize, HG_SMEM);
    cudaFuncSetAttribute(flash_tc_k, cudaFuncAttributeMaxDynamicSharedMemorySize, FLASH_SMEM);

    // fused weight splits (one launch)
    cvt_split_all_k<<<6144, 256>>>(w_qkv, w_proj, w1, w2,
                                   p_wqkv_hi, p_wqkv_lo, p_wproj_hi, p_wproj_lo,
                                   p_w1_hi, p_w1_lo, p_w2_hi, p_w2_lo);

    // LN1 -> hi/lo
    layernorm_bf_k<<<Mm, 256>>>(x, ln1_g, ln1_b, p_h_hi, p_h_lo);

    // QKV GEMM -> bf16 hi only (EPI 4)
    hgemm_k<4><<<dim3(C3 / 128, Mm / 128), 128, HG_SMEM>>>(
        p_h_hi, p_h_lo, p_wqkv_hi, p_wqkv_lo,
        nullptr, p_qkv_hi, nullptr,
        nullptr, nullptr, nullptr, nullptr, nullptr, nullptr,
        C3, Cc);

    // Tensor-core flash attention -> attn hi/lo
    flash_tc_k<<<dim3(Nn / 128, Bz * Hh), 128, FLASH_SMEM>>>(
        p_qkv_hi, p_attn_hi, p_attn_lo);

    // proj GEMM + bias + residual -> x1 fp32 (EPI 1)
    hgemm_k<1><<<dim3(Cc / 128, Mm / 128), 128, HG_SMEM>>>(
        p_attn_hi, p_attn_lo, p_wproj_hi, p_wproj_lo,
        p_x1, nullptr, nullptr,
        b_proj, x, nullptr, nullptr, nullptr, nullptr,
        Cc, Cc);

    // LN2 -> hi/lo
    layernorm_bf_k<<<Mm, 256>>>(p_x1, ln2_g, ln2_b, p_h_hi, p_h_lo);

    // MLP1: ELU(h @ w1^T + b1) -> h1 hi/lo (EPI 2)
    hgemm_k<2><<<dim3(Cc / 128, Mm / 128), 128, HG_SMEM>>>(
        p_h_hi, p_h_lo, p_w1_hi, p_w1_lo,
        nullptr, p_h1_hi, p_h1_lo,
        b1, nullptr, nullptr, nullptr, nullptr, nullptr,
        Cc, Cc);

    // MLP2: out = x1 + BN(ELU(h1 @ w2^T + b2)) (EPI 3)
    hgemm_k<3><<<dim3(Cc / 128, Mm / 128), 128, HG_SMEM>>>(
        p_h1_hi, p_h1_lo, p_w2_hi, p_w2_lo,
        out, nullptr, nullptr,
        b2, p_x1, bn_g, bn_b, bn_mean, bn_var,
        Cc, Cc);
}

// round 16
// speedup vs baseline: 1.5141x; 1.3570x over previous
#include <cuda_runtime.h>
#include <cuda_bf16.h>
#include <math.h>
#include <stdint.h>

// Problem constants
#define Bz   4
#define Nn   2048
#define Cc   1024
#define Hh   8
#define Dd   128
#define Mm   (Bz * Nn)          // 8192 tokens
#define C3   (3 * Cc)           // 3072
#define EPS  1e-5f
#define ATT_SCALE 0.08838834764831845f  // 128^-0.5

// ================= PTX helpers =================
__device__ __forceinline__ uint32_t smem_u32(const void* p) {
    uint32_t a;
    asm("{ .reg .u64 t; cvta.to.shared.u64 t, %1; cvt.u32.u64 %0, t; }" : "=r"(a) : "l"(p));
    return a;
}
#define CP_ASYNC(dst, src) \
    asm volatile("cp.async.cg.shared.global [%0], [%1], 16;" :: "r"(dst), "l"(src))
#define CP_COMMIT() asm volatile("cp.async.commit_group;" ::: "memory")
#define CP_WAIT1()  asm volatile("cp.async.wait_group 1;" ::: "memory")
#define CP_WAIT0()  asm volatile("cp.async.wait_group 0;" ::: "memory")

__device__ __forceinline__ void ldsm_x4(uint32_t& r0, uint32_t& r1, uint32_t& r2, uint32_t& r3,
                                        uint32_t addr) {
    asm volatile("ldmatrix.sync.aligned.m8n8.x4.shared.b16 {%0,%1,%2,%3}, [%4];"
                 : "=r"(r0), "=r"(r1), "=r"(r2), "=r"(r3) : "r"(addr));
}
__device__ __forceinline__ void ldsm_x4_t(uint32_t& r0, uint32_t& r1, uint32_t& r2, uint32_t& r3,
                                          uint32_t addr) {
    asm volatile("ldmatrix.sync.aligned.m8n8.x4.trans.shared.b16 {%0,%1,%2,%3}, [%4];"
                 : "=r"(r0), "=r"(r1), "=r"(r2), "=r"(r3) : "r"(addr));
}
__device__ __forceinline__ void mma_bf16(float* d, const uint32_t* a, const uint32_t* b) {
    asm volatile(
        "mma.sync.aligned.m16n8k16.row.col.f32.bf16.bf16.f32 "
        "{%0,%1,%2,%3}, {%4,%5,%6,%7}, {%8,%9}, {%0,%1,%2,%3};"
        : "+f"(d[0]), "+f"(d[1]), "+f"(d[2]), "+f"(d[3])
        : "r"(a[0]), "r"(a[1]), "r"(a[2]), "r"(a[3]), "r"(b[0]), "r"(b[1]));
}

__device__ __forceinline__ void split2(float a, float b, uint32_t& hp, uint32_t& lp) {
    __nv_bfloat16 ha = __float2bfloat16(a), hb = __float2bfloat16(b);
    float ra = a - __bfloat162float(ha), rb = b - __bfloat162float(hb);
    __nv_bfloat16 la = __float2bfloat16(ra), lb = __float2bfloat16(rb);
    hp = (uint32_t)__bfloat16_as_ushort(ha) | ((uint32_t)__bfloat16_as_ushort(hb) << 16);
    lp = (uint32_t)__bfloat16_as_ushort(la) | ((uint32_t)__bfloat16_as_ushort(lb) << 16);
}
__device__ __forceinline__ uint32_t cvt2bf(float a, float b) {
    __nv_bfloat162 t = __floats2bfloat162_rn(a, b);
    return *(uint32_t*)&t;
}

// ================= scratch (device globals) =================
__device__ float g_x1 [Mm * Cc];
__device__ __nv_bfloat16 g_qkv_hi[Mm * C3];
__device__ __nv_bfloat16 g_h_hi   [Mm * Cc];
__device__ __nv_bfloat16 g_attn_hi[Mm * Cc];
__device__ __nv_bfloat16 g_h1_hi  [Mm * Cc];
__device__ __nv_bfloat16 g_wqkv_hi [C3 * Cc], g_wqkv_lo [C3 * Cc];
__device__ __nv_bfloat16 g_wproj_hi[Cc * Cc], g_wproj_lo[Cc * Cc];
__device__ __nv_bfloat16 g_w1_hi   [Cc * Cc], g_w1_lo   [Cc * Cc];
__device__ __nv_bfloat16 g_w2_hi   [Cc * Cc], g_w2_lo   [Cc * Cc];

// ================= fused fp32 -> bf16 hi/lo converter (all 4 weights) ========
__global__ void cvt_split_all_k(const float* __restrict__ wqkv, const float* __restrict__ wproj,
                                const float* __restrict__ w1, const float* __restrict__ w2,
                                __nv_bfloat16* __restrict__ qkv_hi, __nv_bfloat16* __restrict__ qkv_lo,
                                __nv_bfloat16* __restrict__ proj_hi, __nv_bfloat16* __restrict__ proj_lo,
                                __nv_bfloat16* __restrict__ w1_hi, __nv_bfloat16* __restrict__ w1_lo,
                                __nv_bfloat16* __restrict__ w2_hi, __nv_bfloat16* __restrict__ w2_lo)
{
    int blk = blockIdx.x;
    const float* src;
    __nv_bfloat16 *hi, *lo;
    int local;
    if (blk < 3072)      { src = wqkv;  hi = qkv_hi;  lo = qkv_lo;  local = blk; }
    else if (blk < 4096) { src = wproj; hi = proj_hi; lo = proj_lo; local = blk - 3072; }
    else if (blk < 5120) { src = w1;    hi = w1_hi;   lo = w1_lo;   local = blk - 4096; }
    else                 { src = w2;    hi = w2_hi;   lo = w2_lo;   local = blk - 5120; }
    int i = local * 256 + threadIdx.x;
    float4 v = ((const float4*)src)[i];
    uint32_t h0, l0, h1, l1;
    split2(v.x, v.y, h0, l0);
    split2(v.z, v.w, h1, l1);
    ((uint2*)hi)[i] = make_uint2(h0, h1);
    ((uint2*)lo)[i] = make_uint2(l0, l1);
}

// ================= LayerNorm -> bf16 (hi only) =================
__global__ void layernorm_bf_k(const float* __restrict__ in, const float* __restrict__ g,
                               const float* __restrict__ b,
                               __nv_bfloat16* __restrict__ hi)
{
    int row = blockIdx.x;
    int t = threadIdx.x;
    const float4* inr = (const float4*)(in + (size_t)row * Cc);
    float4 v = inr[t];
    float s  = v.x + v.y + v.z + v.w;
    float ss = v.x*v.x + v.y*v.y + v.z*v.z + v.w*v.w;
    #pragma unroll
    for (int o = 16; o; o >>= 1) {
        s  += __shfl_xor_sync(0xffffffffu, s,  o);
        ss += __shfl_xor_sync(0xffffffffu, ss, o);
    }
    __shared__ float sm1[8], sm2[8];
    if ((t & 31) == 0) { sm1[t >> 5] = s; sm2[t >> 5] = ss; }
    __syncthreads();
    if (t < 32) {
        s  = (t < 8) ? sm1[t] : 0.f;
        ss = (t < 8) ? sm2[t] : 0.f;
        #pragma unroll
        for (int o = 4; o; o >>= 1) {
            s  += __shfl_xor_sync(0xffffffffu, s,  o);
            ss += __shfl_xor_sync(0xffffffffu, ss, o);
        }
        if (t == 0) { sm1[0] = s; sm2[0] = ss; }
    }
    __syncthreads();
    float mu  = sm1[0] * (1.f / Cc);
    float var = sm2[0] * (1.f / Cc) - mu * mu;
    float inv = rsqrtf(var + EPS);
    float4 gv = ((const float4*)g)[t];
    float4 bv = ((const float4*)b)[t];
    float o0 = (v.x - mu) * inv * gv.x + bv.x;
    float o1 = (v.y - mu) * inv * gv.y + bv.y;
    float o2 = (v.z - mu) * inv * gv.z + bv.z;
    float o3 = (v.w - mu) * inv * gv.w + bv.w;
    ((uint2*)(hi + (size_t)row * Cc))[t] = make_uint2(cvt2bf(o0, o1), cvt2bf(o2, o3));
}

// ================= mma.sync 2-term GEMM =================
// C[M,N] = bf16(A)[M,K] @ (Bhi+Blo)[N,K]^T, fp32 accum.
// Tile 128x128, BK=64, 4 warps (2m x 2n, warp tile 64x64), 2 CTAs/SM.
// EPI: 1 +bias+res fp32 | 2 +bias,ELU->bf16 hi | 3 +bias,ELU,BN,+res fp32 | 4 plain->bf16 hi
#define BK      64
#define SSTRIDE 72
#define TILE_B  (128 * SSTRIDE * 2)    // 18432
#define STAGE_B (3 * TILE_B)           // 55296: Ahi | Bhi | Blo
#define HG_SMEM (2 * STAGE_B)          // 110592 -> 2 CTAs/SM (221184 <= 228KB)

template <int EPI>
__global__ __launch_bounds__(128, 2)
void hgemm_k(const __nv_bfloat16* __restrict__ Ahi,
             const __nv_bfloat16* __restrict__ Bhi, const __nv_bfloat16* __restrict__ Blo,
             float* __restrict__ Cf, __nv_bfloat16* __restrict__ Chi,
             const float* __restrict__ bias, const float* __restrict__ res,
             const float* __restrict__ bng, const float* __restrict__ bnb,
             const float* __restrict__ bnm, const float* __restrict__ bnv,
             int Ndim, int Kdim)
{
    extern __shared__ char dsm[];
    const int tid = threadIdx.x;
    const int wid = tid >> 5, lid = tid & 31;
    const int m_blk = blockIdx.y * 128, n_blk = blockIdx.x * 128;
    const int wm = wid >> 1, wn = wid & 1;     // 2m x 2n, warp tile 64x64

    const uint32_t sbase = smem_u32(dsm);

    float acc[4][8][4];
    #pragma unroll
    for (int i = 0; i < 4; i++)
        #pragma unroll
        for (int j = 0; j < 8; j++)
            #pragma unroll
            for (int q = 0; q < 4; q++) acc[i][j][q] = 0.f;

    const int a_row = 64 * wm + (lid & 15);
    const int a_col = (lid >> 4) * 8;
    const int b_row = 64 * wn + ((lid & 16) >> 1) + (lid & 7);
    const int b_col = (lid & 8);

    // stage loader: 3 tiles x 1024 16B-transfers = 3072 over 128 threads -> 24/thread
    auto load_stage = [&](int c) {
        const int kk = c * BK;
        const uint32_t sb = sbase + (c & 1) * STAGE_B;
        #pragma unroll
        for (int it = 0; it < 24; ++it) {
            int id = tid + it * 128;
            int tile = id >> 10;          // compile-time per it
            int loc = id & 1023;
            int row = loc >> 3, seg = loc & 7;
            uint32_t so = (uint32_t)(row * SSTRIDE + seg * 8) * 2 + tile * TILE_B;
            if (tile == 0) {
                CP_ASYNC(sb + so, Ahi + (size_t)(m_blk + row) * Kdim + kk + seg * 8);
            } else if (tile == 1) {
                CP_ASYNC(sb + so, Bhi + (size_t)(n_blk + row) * Kdim + kk + seg * 8);
            } else {
                CP_ASYNC(sb + so, Blo + (size_t)(n_blk + row) * Kdim + kk + seg * 8);
            }
        }
        CP_COMMIT();
    };

    const int nchunk = Kdim / BK;
    load_stage(0);
    for (int c = 0; c < nchunk; ++c) {
        if (c + 1 < nchunk) { load_stage(c + 1); CP_WAIT1(); }
        else                { CP_WAIT0(); }
        __syncthreads();
        const uint32_t sb = sbase + (c & 1) * STAGE_B;
        #pragma unroll
        for (int k16 = 0; k16 < BK / 16; ++k16) {
            uint32_t ah[4][4];
            #pragma unroll
            for (int i = 0; i < 4; ++i) {
                uint32_t ao = sb + (uint32_t)((a_row + 16 * i) * SSTRIDE + a_col + 16 * k16) * 2;
                ldsm_x4(ah[i][0], ah[i][1], ah[i][2], ah[i][3], ao);
            }
            #pragma unroll
            for (int jj = 0; jj < 4; ++jj) {
                uint32_t bh[2][2], bl[2][2];
                uint32_t bo = sb + TILE_B
                            + (uint32_t)((16 * jj + b_row) * SSTRIDE + b_col + 16 * k16) * 2;
                ldsm_x4(bh[0][0], bh[0][1], bh[1][0], bh[1][1], bo);
                ldsm_x4(bl[0][0], bl[0][1], bl[1][0], bl[1][1], bo + TILE_B);
                #pragma unroll
                for (int i = 0; i < 4; ++i) {
                    #pragma unroll
                    for (int t = 0; t < 2; ++t) {
                        mma_bf16(acc[i][2*jj + t], ah[i], bh[t]);
                        mma_bf16(acc[i][2*jj + t], ah[i], bl[t]);
                    }
                }
            }
        }
        __syncthreads();
    }

    #pragma unroll
    for (int i = 0; i < 4; ++i) {
        #pragma unroll
        for (int half = 0; half < 2; ++half) {
            const int r = m_blk + 64 * wm + 16 * i + (lid >> 2) + 8 * half;
            #pragma unroll
            for (int j = 0; j < 8; ++j) {
                const int c = n_blk + 64 * wn + 8 * j + 2 * (lid & 3);
                float v0 = acc[i][j][2 * half + 0];
                float v1 = acc[i][j][2 * half + 1];
                if (EPI == 1) {
                    const float2 rv = *(const float2*)(res + (size_t)r * Ndim + c);
                    v0 += __ldg(bias + c)     + rv.x;
                    v1 += __ldg(bias + c + 1) + rv.y;
                } else if (EPI == 2) {
                    v0 += __ldg(bias + c);
                    v1 += __ldg(bias + c + 1);
                    v0 = (v0 > 0.f) ? v0 : expm1f(v0);
                    v1 = (v1 > 0.f) ? v1 : expm1f(v1);
                } else if (EPI == 3) {
                    const float2 rv = *(const float2*)(res + (size_t)r * Ndim + c);
                    v0 += __ldg(bias + c);
                    v1 += __ldg(bias + c + 1);
                    v0 = (v0 > 0.f) ? v0 : expm1f(v0);
                    v1 = (v1 > 0.f) ? v1 : expm1f(v1);
                    v0 = (v0 - __ldg(bnm + c))     * rsqrtf(__ldg(bnv + c) + EPS)     * __ldg(bng + c)     + __ldg(bnb + c)     + rv.x;
                    v1 = (v1 - __ldg(bnm + c + 1)) * rsqrtf(__ldg(bnv + c + 1) + EPS) * __ldg(bng + c + 1) + __ldg(bnb + c + 1) + rv.y;
                }
                if (EPI == 2 || EPI == 4) {
                    *(uint32_t*)(Chi + (size_t)r * Ndim + c) = cvt2bf(v0, v1);
                } else {
                    *(float2*)(Cf + (size_t)r * Ndim + c) = make_float2(v0, v1);
                }
            }
        }
    }
}

// ================= Tensor-core flash attention =================
// BQ=128, BK=64, 4 warps x 32 q-rows, 128 threads, 2 CTAs/SM. Writes bf16 hi only.
#define FQSTR     136
#define FQ_B      (128 * FQSTR * 2)        // 34816
#define FK_B      (64 * FQSTR * 2)         // 17408
#define FSTAGE_B  (2 * FK_B)               // 34816
#define FLASH_SMEM (FQ_B + 2 * FSTAGE_B)   // 104448 -> 2 CTAs/SM

__global__ __launch_bounds__(128, 2)
void flash_tc_k(const __nv_bfloat16* __restrict__ qkv_hi,
                __nv_bfloat16* __restrict__ out_hi)
{
    extern __shared__ char fsm[];
    const int tid = threadIdx.x, wid = tid >> 5, lid = tid & 31;
    const int bh_i = blockIdx.y, b = bh_i >> 3, h = bh_i & 7;
    const int q0 = blockIdx.x * 128;
    const size_t base = (size_t)b * Nn * C3 + h * Dd;

    const uint32_t sQ  = smem_u32(fsm);
    const uint32_t sKV = sQ + FQ_B;

    #pragma unroll
    for (int it = 0; it < 16; ++it) {
        int idx = tid + it * 128;
        int row = idx >> 4, seg = idx & 15;
        uint32_t so = (uint32_t)row * (FQSTR * 2) + seg * 16;
        CP_ASYNC(sQ + so, qkv_hi + base + (size_t)(q0 + row) * C3 + seg * 8);
    }

    auto load_kv = [&](int kt) {
        const uint32_t sb = sKV + (kt & 1) * FSTAGE_B;
        #pragma unroll
        for (int it = 0; it < 8; ++it) {
            int idx = tid + it * 128;
            int row = idx >> 4, seg = idx & 15;
            uint32_t so = (uint32_t)row * (FQSTR * 2) + seg * 16;
            size_t gk = base + (size_t)(kt * 64 + row) * C3 + Cc + seg * 8;
            size_t gv = base + (size_t)(kt * 64 + row) * C3 + 2 * Cc + seg * 8;
            CP_ASYNC(sb + so,        qkv_hi + gk);
            CP_ASYNC(sb + FK_B + so, qkv_hi + gv);
        }
        CP_COMMIT();
    };

    load_kv(0);

    const float SCL = ATT_SCALE * 1.4426950408889634f;
    float mst[2][2], lst[2][2];
    #pragma unroll
    for (int m = 0; m < 2; ++m) {
        mst[m][0] = -1e30f; mst[m][1] = -1e30f;
        lst[m][0] = 0.f;    lst[m][1] = 0.f;
    }
    float accO[2][16][4];
    #pragma unroll
    for (int m = 0; m < 2; ++m)
        #pragma unroll
        for (int j = 0; j < 16; ++j)
            #pragma unroll
            for (int q = 0; q < 4; ++q) accO[m][j][q] = 0.f;

    const int b_rl = ((lid & 16) >> 1) + (lid & 7);
    const int b_cl = (lid & 8);
    const int v_rl = (lid & 8) + (lid & 7);
    const int v_cl = ((lid & 16) >> 1);

    const int NT = Nn / 64;
    for (int kt = 0; kt < NT; ++kt) {
        if (kt + 1 < NT) { load_kv(kt + 1); CP_WAIT1(); }
        else             { CP_WAIT0(); }
        __syncthreads();
        const uint32_t sb = sKV + (kt & 1) * FSTAGE_B;

        float accS[2][8][4];
        #pragma unroll
        for (int m = 0; m < 2; ++m)
            #pragma unroll
            for (int j = 0; j < 8; ++j)
                #pragma unroll
                for (int q = 0; q < 4; ++q) accS[m][j][q] = 0.f;

        #pragma unroll
        for (int k16 = 0; k16 < 8; ++k16) {
            uint32_t ah[2][4];
            #pragma unroll
            for (int m = 0; m < 2; ++m) {
                uint32_t ao = sQ + (uint32_t)((32 * wid + 16 * m + (lid & 15)) * FQSTR
                                              + (lid >> 4) * 8 + 16 * k16) * 2;
                ldsm_x4(ah[m][0], ah[m][1], ah[m][2], ah[m][3], ao);
            }
            #pragma unroll
            for (int jj = 0; jj < 4; ++jj) {
                uint32_t bh[2][2];
                uint32_t bo = sb + (uint32_t)((16 * jj + b_rl) * FQSTR + b_cl + 16 * k16) * 2;
                ldsm_x4(bh[0][0], bh[0][1], bh[1][0], bh[1][1], bo);
                #pragma unroll
                for (int m = 0; m < 2; ++m) {
                    mma_bf16(accS[m][2*jj],     ah[m], bh[0]);
                    mma_bf16(accS[m][2*jj + 1], ah[m], bh[1]);
                }
            }
        }

        uint32_t pa[2][4][4];
        #pragma unroll
        for (int m = 0; m < 2; ++m) {
            float mx0 = -1e30f, mx1 = -1e30f;
            #pragma unroll
            for (int j = 0; j < 8; ++j) {
                mx0 = fmaxf(mx0, fmaxf(accS[m][j][0], accS[m][j][1]));
                mx1 = fmaxf(mx1, fmaxf(accS[m][j][2], accS[m][j][3]));
            }
            mx0 = fmaxf(mx0, __shfl_xor_sync(0xffffffffu, mx0, 1));
            mx0 = fmaxf(mx0, __shfl_xor_sync(0xffffffffu, mx0, 2));
            mx1 = fmaxf(mx1, __shfl_xor_sync(0xffffffffu, mx1, 1));
            mx1 = fmaxf(mx1, __shfl_xor_sync(0xffffffffu, mx1, 2));
            mx0 *= SCL; mx1 *= SCL;
            float mn0 = fmaxf(mst[m][0], mx0), mn1 = fmaxf(mst[m][1], mx1);
            float al0 = exp2f(mst[m][0] - mn0), al1 = exp2f(mst[m][1] - mn1);
            mst[m][0] = mn0; mst[m][1] = mn1;

            float ls0 = 0.f, ls1 = 0.f;
            #pragma unroll
            for (int j = 0; j < 8; ++j) {
                float p0 = exp2f(accS[m][j][0] * SCL - mn0);
                float p1 = exp2f(accS[m][j][1] * SCL - mn0);
                float p2 = exp2f(accS[m][j][2] * SCL - mn1);
                float p3 = exp2f(accS[m][j][3] * SCL - mn1);
                accS[m][j][0] = p0; accS[m][j][1] = p1;
                accS[m][j][2] = p2; accS[m][j][3] = p3;
                ls0 += p0 + p1; ls1 += p2 + p3;
            }
            ls0 += __shfl_xor_sync(0xffffffffu, ls0, 1);
            ls0 += __shfl_xor_sync(0xffffffffu, ls0, 2);
            ls1 += __shfl_xor_sync(0xffffffffu, ls1, 1);
            ls1 += __shfl_xor_sync(0xffffffffu, ls1, 2);
            lst[m][0] = lst[m][0] * al0 + ls0;
            lst[m][1] = lst[m][1] * al1 + ls1;

            #pragma unroll
            for (int j = 0; j < 16; ++j) {
                accO[m][j][0] *= al0; accO[m][j][1] *= al0;
                accO[m][j][2] *= al1; accO[m][j][3] *= al1;
            }

            #pragma unroll
            for (int kk = 0; kk < 4; ++kk) {
                pa[m][kk][0] = cvt2bf(accS[m][2*kk][0],   accS[m][2*kk][1]);
                pa[m][kk][1] = cvt2bf(accS[m][2*kk][2],   accS[m][2*kk][3]);
                pa[m][kk][2] = cvt2bf(accS[m][2*kk+1][0], accS[m][2*kk+1][1]);
                pa[m][kk][3] = cvt2bf(accS[m][2*kk+1][2], accS[m][2*kk+1][3]);
            }
        }

        #pragma unroll
        for (int kk = 0; kk < 4; ++kk) {
            #pragma unroll
            for (int jj = 0; jj < 8; ++jj) {
                uint32_t r0, r1, r2, r3;
                uint32_t vo = sb + FK_B
                            + (uint32_t)((16 * kk + v_rl) * FQSTR + 16 * jj + v_cl) * 2;
                ldsm_x4_t(r0, r1, r2, r3, vo);
                uint32_t vb0[2] = {r0, r1}, vb1[2] = {r2, r3};
                #pragma unroll
                for (int m = 0; m < 2; ++m) {
                    mma_bf16(accO[m][2*jj],     pa[m][kk], vb0);
                    mma_bf16(accO[m][2*jj + 1], pa[m][kk], vb1);
                }
            }
        }
        __syncthreads();
    }

    #pragma unroll
    for (int m = 0; m < 2; ++m) {
        float inv0 = 1.f / lst[m][0], inv1 = 1.f / lst[m][1];
        const int row0 = q0 + 32 * wid + 16 * m + (lid >> 2);
        #pragma unroll
        for (int j = 0; j < 16; ++j) {
            const int col = h * Dd + 8 * j + 2 * (lid & 3);
            size_t o0 = ((size_t)b * Nn + row0) * Cc + col;
            *(uint32_t*)(out_hi + o0) = cvt2bf(accO[m][j][0] * inv0, accO[m][j][1] * inv0);
            size_t o1 = ((size_t)b * Nn + row0 + 8) * Cc + col;
            *(uint32_t*)(out_hi + o1) = cvt2bf(accO[m][j][2] * inv1, accO[m][j][3] * inv1);
        }
    }
}

// ================= host launcher =================
extern "C" void kernel_launch(void* const* d_in, const int* in_sizes, int n_in,
                              void* d_out, int out_size)
{
    const float* x       = (const float*)d_in[0];
    const float* ln1_g   = (const float*)d_in[1];
    const float* ln1_b   = (const float*)d_in[2];
    const float* w_qkv   = (const float*)d_in[3];
    const float* w_proj  = (const float*)d_in[4];
    const float* b_proj  = (const float*)d_in[5];
    const float* ln2_g   = (const float*)d_in[6];
    const float* ln2_b   = (const float*)d_in[7];
    const float* w1      = (const float*)d_in[8];
    const float* b1      = (const float*)d_in[9];
    const float* w2      = (const float*)d_in[10];
    const float* b2      = (const float*)d_in[11];
    const float* bn_g    = (const float*)d_in[12];
    const float* bn_b    = (const float*)d_in[13];
    const float* bn_mean = (const float*)d_in[14];
    const float* bn_var  = (const float*)d_in[15];
    float* out = (float*)d_out;

    float *p_x1;
    __nv_bfloat16 *p_qkv_hi;
    __nv_bfloat16 *p_h_hi, *p_attn_hi, *p_h1_hi;
    __nv_bfloat16 *p_wqkv_hi, *p_wqkv_lo, *p_wproj_hi, *p_wproj_lo;
    __nv_bfloat16 *p_w1_hi, *p_w1_lo, *p_w2_hi, *p_w2_lo;
    cudaGetSymbolAddress((void**)&p_x1,       g_x1);
    cudaGetSymbolAddress((void**)&p_qkv_hi,   g_qkv_hi);
    cudaGetSymbolAddress((void**)&p_h_hi,     g_h_hi);
    cudaGetSymbolAddress((void**)&p_attn_hi,  g_attn_hi);
    cudaGetSymbolAddress((void**)&p_h1_hi,    g_h1_hi);
    cudaGetSymbolAddress((void**)&p_wqkv_hi,  g_wqkv_hi);
    cudaGetSymbolAddress((void**)&p_wqkv_lo,  g_wqkv_lo);
    cudaGetSymbolAddress((void**)&p_wproj_hi, g_wproj_hi);
    cudaGetSymbolAddress((void**)&p_wproj_lo, g_wproj_lo);
    cudaGetSymbolAddress((void**)&p_w1_hi,    g_w1_hi);
    cudaGetSymbolAddress((void**)&p_w1_lo,    g_w1_lo);
    cudaGetSymbolAddress((void**)&p_w2_hi,    g_w2_hi);
    cudaGetSymbolAddress((void**)&p_w2_lo,    g_w2_lo);

    cudaFuncSetAttribute(hgemm_k<1>, cudaFuncAttributeMaxDynamicSharedMemorySize, HG_SMEM);
    cudaFuncSetAttribute(hgemm_k<2>, cudaFuncAttributeMaxDynamicSharedMemorySize, HG_SMEM);
    cudaFuncSetAttribute(hgemm_k<3>, cudaFuncAttributeMaxDynamicSharedMemorySize, HG_SMEM);
    cudaFuncSetAttribute(hgemm_k<4>, cudaFuncAttributeMaxDynamicSharedMemorySize, HG_SMEM);
    cudaFuncSetAttribute(flash_tc_k, cudaFuncAttributeMaxDynamicSharedMemorySize, FLASH_SMEM);

    // fused weight splits (one launch)
    cvt_split_all_k<<<6144, 256>>>(w_qkv, w_proj, w1, w2,
                                   p_wqkv_hi, p_wqkv_lo, p_wproj_hi, p_wproj_lo,
                                   p_w1_hi, p_w1_lo, p_w2_hi, p_w2_lo);

    // LN1 -> bf16 hi
    layernorm_bf_k<<<Mm, 256>>>(x, ln1_g, ln1_b, p_h_hi);

    // QKV GEMM -> bf16 hi (EPI 4)
    hgemm_k<4><<<dim3(C3 / 128, Mm / 128), 128, HG_SMEM>>>(
        p_h_hi, p_wqkv_hi, p_wqkv_lo,
        nullptr, p_qkv_hi,
        nullptr, nullptr, nullptr, nullptr, nullptr, nullptr,
        C3, Cc);

    // Tensor-core flash attention -> attn bf16 hi
    flash_tc_k<<<dim3(Nn / 128, Bz * Hh), 128, FLASH_SMEM>>>(
        p_qkv_hi, p_attn_hi);

    // proj GEMM + bias + residual -> x1 fp32 (EPI 1)
    hgemm_k<1><<<dim3(Cc / 128, Mm / 128), 128, HG_SMEM>>>(
        p_attn_hi, p_wproj_hi, p_wproj_lo,
        p_x1, nullptr,
        b_proj, x, nullptr, nullptr, nullptr, nullptr,
        Cc, Cc);

    // LN2 -> bf16 hi
    layernorm_bf_k<<<Mm, 256>>>(p_x1, ln2_g, ln2_b, p_h_hi);

    // MLP1: ELU(h @ w1^T + b1) -> h1 bf16 hi (EPI 2)
    hgemm_k<2><<<dim3(Cc / 128, Mm / 128), 128, HG_SMEM>>>(
        p_h_hi, p_w1_hi, p_w1_lo,
        nullptr, p_h1_hi,
        b1, nullptr, nullptr, nullptr, nullptr, nullptr,
        Cc, Cc);

    // MLP2: out = x1 + BN(ELU(h1 @ w2^T + b2)) (EPI 3)
    hgemm_k<3><<<dim3(Cc / 128, Mm / 128), 128, HG_SMEM>>>(
        p_h1_hi, p_w2_hi, p_w2_lo,
        out, nullptr,
        b2, p_x1, bn_g, bn_b, bn_mean, bn_var,
        Cc, Cc);
}